// round 2
// baseline (speedup 1.0000x reference)
#include <cuda_runtime.h>
#include <cstdint>
#include <cstddef>

// Problem dims
#define CB 32
#define CN 1024
#define CD 512
#define CH 8
// BN = CB*CN = 32768

// ---------------- scratch (device globals; allocation-free rule) ----------------
__device__ float g_kh[134217728];   // [H][B*N][D] 512MB
__device__ float g_vh[134217728];   // [H][B*N][D]
__device__ float g_qh[134217728];   // [H][B*N][D]
__device__ float g_sc[268435456];   // [B*H][N][N] 1GB  (scores -> probs in place)
__device__ float g_cat[134217728];  // [B*N][H][D] 512MB (concat layout, head-major)
__device__ float g_wo[2097152];     // [D][H*D] permuted Wo (col h*D+d)

// ---------------- helpers ----------------
__device__ __forceinline__ void tf32_split_u(float x, unsigned& hi, unsigned& lo) {
    asm("cvt.rna.tf32.f32 %0, %1;" : "=r"(hi) : "f"(x));
    float l = x - __uint_as_float(hi);
    asm("cvt.rna.tf32.f32 %0, %1;" : "=r"(lo) : "f"(l));
}

__device__ __forceinline__ void mma_tf32(float c[4],
                                         unsigned a0, unsigned a1, unsigned a2, unsigned a3,
                                         unsigned b0, unsigned b1) {
    asm volatile(
        "mma.sync.aligned.m16n8k8.row.col.f32.tf32.tf32.f32 "
        "{%0,%1,%2,%3},{%4,%5,%6,%7},{%8,%9},{%0,%1,%2,%3};\n"
        : "+f"(c[0]), "+f"(c[1]), "+f"(c[2]), "+f"(c[3])
        : "r"(a0), "r"(a1), "r"(a2), "r"(a3), "r"(b0), "r"(b1));
}

__device__ __forceinline__ void cpa16(uint32_t dst, const void* src) {
    asm volatile("cp.async.cg.shared.global [%0], [%1], 16;\n" :: "r"(dst), "l"(src));
}
__device__ __forceinline__ void cpa_commit() { asm volatile("cp.async.commit_group;\n" ::: "memory"); }
__device__ __forceinline__ void cpa_wait0()  { asm volatile("cp.async.wait_group 0;\n" ::: "memory"); }

// ---------------- generic 3xTF32 GEMM ----------------
// C[m,n] = sum_k A[m,k] * B'[k,n] ; NT: B is [N',K], NN: B is [K,N'].
// Tile 128x64x16, 256 threads (8 warps: 4 M x 2 N), warp tile 32x32.
// Raw fp32 in smem via cp.async (2-stage); 3xTF32 split at fragment-load time.
// MODE 0: per-head projection  Y[h] = X @ W[h]^T + b[h]   (z = head, SEL picks out buffer)
// MODE 1: scores S = qh @ kh^T                            (z = b*H+h)
// MODE 2: O = P @ vh (NN), scatter rows into cat layout   (z = b*H+h)
// MODE 3: out = cat' @ Wo'^T + bo                         (z = 0)

#define BM 128
#define BNT 64
#define BK 16
#define AROW 20          // BK + 4 pad (floats)
#define BROW_NT 20       // BK + 4 pad
#define BROW_NN 68       // BNT + 4 pad

template<int MODE, int SEL>
__global__ __launch_bounds__(256, 2)
void gemm3t(const float* __restrict__ P0, const float* __restrict__ P1,
            const float* __restrict__ PB, float* __restrict__ PO)
{
    constexpr long BNrows = (long)CB * CN;                 // 32768
    constexpr int KD  = (MODE == 2) ? 1024 : (MODE == 3 ? 4096 : 512);
    constexpr int LDA = (MODE == 2) ? 1024 : (MODE == 3 ? 4096 : 512);
    constexpr int LDB = (MODE == 3) ? 4096 : 512;
    constexpr int LDC = (MODE == 1) ? 1024 : (MODE == 2 ? 4096 : 512);
    constexpr bool NT   = (MODE != 2);
    constexpr bool HASB = (MODE == 0 || MODE == 3);
    constexpr int ABUF = BM * AROW;                         // floats per A stage
    constexpr int BBUF = NT ? (BNT * BROW_NT) : (BK * BROW_NN);

    const int z = blockIdx.z;
    const float* A;
    const float* Bm;
    const float* bias = nullptr;
    float* C;

    if constexpr (MODE == 0) {
        A   = P0;
        Bm  = P1 + (size_t)z * 512 * 512;
        bias = PB + (size_t)z * 512;
        float* ob = (SEL == 0) ? g_kh : (SEL == 1) ? g_vh : g_qh;
        C = ob + (size_t)z * BNrows * 512;
    } else if constexpr (MODE == 1) {
        const int b = z >> 3, h = z & 7;
        const size_t off = ((size_t)h * BNrows + (size_t)b * CN) * 512;
        A  = g_qh + off;
        Bm = g_kh + off;
        C  = g_sc + (size_t)z * CN * CN;
    } else if constexpr (MODE == 2) {
        const int b = z >> 3, h = z & 7;
        A  = g_sc + (size_t)z * CN * CN;
        Bm = g_vh + ((size_t)h * BNrows + (size_t)b * CN) * 512;
        C  = g_cat + ((size_t)b * CN * CH + h) * 512;
    } else {
        A = g_cat; Bm = g_wo; bias = PB; C = PO;
    }

    const int m0 = blockIdx.y * BM;
    const int n0 = blockIdx.x * BNT;
    const int tid = threadIdx.x;

    __shared__ __align__(16) float As[2 * ABUF];
    __shared__ __align__(16) float Bs[2 * BBUF];

    const uint32_t as_base = (uint32_t)__cvta_generic_to_shared(&As[0]);
    const uint32_t bs_base = (uint32_t)__cvta_generic_to_shared(&Bs[0]);

    // ---- cp.async source/dest mappings ----
    // A: 128 rows x 16 k = 512 float4; thread does chunks tid and tid+256.
    const int a_r  = tid >> 2;            // 0..63
    const int a_kq = (tid & 3) * 4;       // 0,4,8,12
    const float* aSrc0 = A + (size_t)(m0 + a_r) * LDA + a_kq;
    const float* aSrc1 = A + (size_t)(m0 + a_r + 64) * LDA + a_kq;
    const uint32_t aDst0 = as_base + (uint32_t)(a_r * AROW + a_kq) * 4u;
    const uint32_t aDst1 = aDst0 + (uint32_t)(64 * AROW) * 4u;

    // B: 256 float4, one per thread.
    const float* bSrc;
    uint32_t bDst;
    if constexpr (NT) {               // B[n0+r][t*BK + kq..+3] -> Bs[r][kq..]
        const int b_r  = tid >> 2;    // 0..63
        const int b_kq = (tid & 3) * 4;
        bSrc = Bm + (size_t)(n0 + b_r) * LDB + b_kq;
        bDst = bs_base + (uint32_t)(b_r * BROW_NT + b_kq) * 4u;
    } else {                          // B[t*BK+kr][n0+nq..+3] -> Bs[kr][nq..]
        const int b_kr = tid >> 4;    // 0..15
        const int b_nq = (tid & 15) * 4;
        bSrc = Bm + (size_t)b_kr * LDB + n0 + b_nq;
        bDst = bs_base + (uint32_t)(b_kr * BROW_NN + b_nq) * 4u;
    }

    const int warp = tid >> 5, lane = tid & 31;
    const int wm = (warp & 3) * 32;
    const int wn = (warp >> 2) * 32;
    const int grp = lane >> 2, qd = lane & 3;

    float acc[2][4][4];
    #pragma unroll
    for (int i = 0; i < 2; i++)
        #pragma unroll
        for (int j = 0; j < 4; j++)
            #pragma unroll
            for (int t = 0; t < 4; t++) acc[i][j][t] = 0.f;

    // ---- prologue: issue tile 0 into buffer 0 ----
    {
        cpa16(aDst0, aSrc0);
        cpa16(aDst1, aSrc1);
        if constexpr (NT) cpa16(bDst, bSrc);
        else              cpa16(bDst, bSrc);
        cpa_commit();
    }

    const int ktiles = KD / BK;
    for (int t = 0; t < ktiles; ++t) {
        const int cur = t & 1;
        cpa_wait0();
        __syncthreads();

        if (t + 1 < ktiles) {
            const int nxt = cur ^ 1;
            const size_t koff = (size_t)(t + 1) * BK;
            cpa16(aDst0 + (uint32_t)(nxt * ABUF) * 4u, aSrc0 + koff);
            cpa16(aDst1 + (uint32_t)(nxt * ABUF) * 4u, aSrc1 + koff);
            if constexpr (NT) cpa16(bDst + (uint32_t)(nxt * BBUF) * 4u, bSrc + koff);
            else              cpa16(bDst + (uint32_t)(nxt * BBUF) * 4u, bSrc + koff * LDB);
            cpa_commit();
        }

        const float* as = &As[cur * ABUF];
        const float* bs = &Bs[cur * BBUF];

        #pragma unroll
        for (int ks = 0; ks < 2; ++ks) {
            const int k0 = ks * 8 + qd;
            const int k1 = k0 + 4;

            unsigned ah[2][4], al[2][4];
            #pragma unroll
            for (int fm = 0; fm < 2; fm++) {
                const int r0 = wm + fm * 16 + grp;
                tf32_split_u(as[r0 * AROW + k0],       ah[fm][0], al[fm][0]);
                tf32_split_u(as[(r0 + 8) * AROW + k0], ah[fm][1], al[fm][1]);
                tf32_split_u(as[r0 * AROW + k1],       ah[fm][2], al[fm][2]);
                tf32_split_u(as[(r0 + 8) * AROW + k1], ah[fm][3], al[fm][3]);
            }
            unsigned bh[4][2], bl[4][2];
            #pragma unroll
            for (int fn = 0; fn < 4; fn++) {
                const int c = wn + fn * 8 + grp;
                float w0, w1;
                if constexpr (NT) { w0 = bs[c * BROW_NT + k0]; w1 = bs[c * BROW_NT + k1]; }
                else              { w0 = bs[k0 * BROW_NN + c]; w1 = bs[k1 * BROW_NN + c]; }
                tf32_split_u(w0, bh[fn][0], bl[fn][0]);
                tf32_split_u(w1, bh[fn][1], bl[fn][1]);
            }

            #pragma unroll
            for (int fm = 0; fm < 2; fm++) {
                #pragma unroll
                for (int fn = 0; fn < 4; fn++) {
                    mma_tf32(acc[fm][fn], ah[fm][0], ah[fm][1], ah[fm][2], ah[fm][3],
                             bh[fn][0], bh[fn][1]);                       // hi*hi
                    mma_tf32(acc[fm][fn], ah[fm][0], ah[fm][1], ah[fm][2], ah[fm][3],
                             bl[fn][0], bl[fn][1]);                       // hi*lo
                    mma_tf32(acc[fm][fn], al[fm][0], al[fm][1], al[fm][2], al[fm][3],
                             bh[fn][0], bh[fn][1]);                       // lo*hi
                }
            }
        }
        // no trailing sync: next-iter wait+syncthreads orders reuse of this buffer
    }

    // ---- epilogue ----
    #pragma unroll
    for (int fm = 0; fm < 2; fm++) {
        const int r = m0 + wm + fm * 16 + grp;
        #pragma unroll
        for (int fn = 0; fn < 4; fn++) {
            const int cc = n0 + wn + fn * 8 + qd * 2;
            float2 v0 = make_float2(acc[fm][fn][0], acc[fm][fn][1]);
            float2 v1 = make_float2(acc[fm][fn][2], acc[fm][fn][3]);
            if constexpr (HASB) {
                const float2 bb = *(const float2*)(bias + cc);
                v0.x += bb.x; v0.y += bb.y; v1.x += bb.x; v1.y += bb.y;
            }
            *(float2*)(C + (size_t)r * LDC + cc)       = v0;
            *(float2*)(C + (size_t)(r + 8) * LDC + cc) = v1;
        }
    }
}

// ---------------- softmax over score rows (scale folded in) ----------------
__global__ void softmax_k()
{
    const size_t row = blockIdx.x;                    // B*H*N = 262144 rows
    float* p = g_sc + row * 1024;
    const int tid = threadIdx.x;                      // 256 threads, 4 elems each
    float4 v = reinterpret_cast<float4*>(p)[tid];

    float m = fmaxf(fmaxf(v.x, v.y), fmaxf(v.z, v.w));
    #pragma unroll
    for (int o = 16; o; o >>= 1) m = fmaxf(m, __shfl_xor_sync(0xffffffffu, m, o));
    __shared__ float sm[8];
    if ((tid & 31) == 0) sm[tid >> 5] = m;
    __syncthreads();
    const float mm = fmaxf(fmaxf(fmaxf(sm[0], sm[1]), fmaxf(sm[2], sm[3])),
                           fmaxf(fmaxf(sm[4], sm[5]), fmaxf(sm[6], sm[7])));

    const float INV_TAU = 0.044194173824159216f;      // 1/sqrt(512)
    v.x = __expf((v.x - mm) * INV_TAU);
    v.y = __expf((v.y - mm) * INV_TAU);
    v.z = __expf((v.z - mm) * INV_TAU);
    v.w = __expf((v.w - mm) * INV_TAU);

    float s = v.x + v.y + v.z + v.w;
    #pragma unroll
    for (int o = 16; o; o >>= 1) s += __shfl_xor_sync(0xffffffffu, s, o);
    __shared__ float ss[8];
    if ((tid & 31) == 0) ss[tid >> 5] = s;
    __syncthreads();
    const float tot = ss[0] + ss[1] + ss[2] + ss[3] + ss[4] + ss[5] + ss[6] + ss[7];

    const float inv = 1.0f / tot;
    v.x *= inv; v.y *= inv; v.z *= inv; v.w *= inv;
    reinterpret_cast<float4*>(p)[tid] = v;
}

// ---------------- Wo column permutation: col d*H+h -> h*D+d ----------------
__global__ void permute_wo(const float* __restrict__ Wo)
{
    const int i = blockIdx.x * blockDim.x + threadIdx.x;  // 512*4096 = 2097152
    if (i >= 512 * 4096) return;
    const int e2 = i >> 12;
    const int c  = i & 4095;
    const int h  = c >> 9;
    const int d  = c & 511;
    g_wo[i] = Wo[(e2 << 12) + d * 8 + h];
}

// ---------------- launch ----------------
extern "C" void kernel_launch(void* const* d_in, const int* in_sizes, int n_in,
                              void* d_out, int out_size)
{
    (void)in_sizes; (void)n_in; (void)out_size;
    const float* k  = (const float*)d_in[0];
    const float* v  = (const float*)d_in[1];
    const float* q  = (const float*)d_in[2];
    const float* Wk = (const float*)d_in[3];
    const float* bk = (const float*)d_in[4];
    const float* Wv = (const float*)d_in[5];
    const float* bv = (const float*)d_in[6];
    const float* Wq = (const float*)d_in[7];
    const float* bq = (const float*)d_in[8];
    const float* Wo = (const float*)d_in[9];
    const float* bo = (const float*)d_in[10];
    float* out = (float*)d_out;

    const dim3 blk(256);

    permute_wo<<<8192, 256>>>(Wo);

    // per-head projections: grid (N'/64=8, M/128=256, H=8)
    gemm3t<0, 0><<<dim3(8, 256, 8), blk>>>(k, Wk, bk, nullptr);
    gemm3t<0, 1><<<dim3(8, 256, 8), blk>>>(v, Wv, bv, nullptr);
    gemm3t<0, 2><<<dim3(8, 256, 8), blk>>>(q, Wq, bq, nullptr);

    // scores: grid (1024/64=16, 1024/128=8, B*H=256)
    gemm3t<1, 0><<<dim3(16, 8, 256), blk>>>(nullptr, nullptr, nullptr, nullptr);

    // softmax over 262144 rows
    softmax_k<<<262144, 256>>>();

    // PV: grid (512/64=8, 1024/128=8, 256)
    gemm3t<2, 0><<<dim3(8, 8, 256), blk>>>(nullptr, nullptr, nullptr, nullptr);

    // output projection: grid (512/64=8, 32768/128=256, 1)
    gemm3t<3, 0><<<dim3(8, 256, 1), blk>>>(nullptr, nullptr, bo, out);
}

// round 3
// speedup vs baseline: 1.3846x; 1.3846x over previous
#include <cuda_runtime.h>
#include <cstdint>
#include <cstddef>

// Problem dims
#define CB 32
#define CN 1024
#define CD 512
#define CH 8
// BN = CB*CN = 32768

// ---------------- scratch (device globals; allocation-free rule) ----------------
__device__ float g_kh[134217728];   // [H][B*N][D] 512MB
__device__ float g_vh[134217728];   // [H][B*N][D]
__device__ float g_qh[134217728];   // [H][B*N][D]
__device__ float g_sc[268435456];   // [B*H][N][N] 1GB  (scores -> probs in place)
__device__ float g_cat[134217728];  // [B*N][H][D] 512MB (concat layout, head-major)
__device__ float g_wo[2097152];     // [D][H*D] permuted Wo (col h*D+d)

// ---------------- helpers ----------------
__device__ __forceinline__ unsigned tf32_hi(float x) {
    unsigned h;
    asm("cvt.rna.tf32.f32 %0, %1;" : "=r"(h) : "f"(x));
    return h;
}
__device__ __forceinline__ void tf32_split_u(float x, unsigned& hi, unsigned& lo) {
    asm("cvt.rna.tf32.f32 %0, %1;" : "=r"(hi) : "f"(x));
    float l = x - __uint_as_float(hi);
    asm("cvt.rna.tf32.f32 %0, %1;" : "=r"(lo) : "f"(l));
}

__device__ __forceinline__ void mma_tf32(float c[4],
                                         unsigned a0, unsigned a1, unsigned a2, unsigned a3,
                                         unsigned b0, unsigned b1) {
    asm volatile(
        "mma.sync.aligned.m16n8k8.row.col.f32.tf32.tf32.f32 "
        "{%0,%1,%2,%3},{%4,%5,%6,%7},{%8,%9},{%0,%1,%2,%3};\n"
        : "+f"(c[0]), "+f"(c[1]), "+f"(c[2]), "+f"(c[3])
        : "r"(a0), "r"(a1), "r"(a2), "r"(a3), "r"(b0), "r"(b1));
}

__device__ __forceinline__ void cpa16(uint32_t dst, const void* src) {
    asm volatile("cp.async.cg.shared.global [%0], [%1], 16;\n" :: "r"(dst), "l"(src));
}
__device__ __forceinline__ void cpa_commit() { asm volatile("cp.async.commit_group;\n" ::: "memory"); }
__device__ __forceinline__ void cpa_wait0()  { asm volatile("cp.async.wait_group 0;\n" ::: "memory"); }

// ---------------- 2xTF32 GEMM (A single-tf32, B hi/lo split) ----------------
// C[m,n] = sum_k A[m,k] * B'[k,n] ; NT: B is [N',K], NN: B is [K,N'].
// Tile 128x64x16, 256 threads (8 warps: 4 M x 2 N), warp tile 32x32.
// Raw fp32 in smem via cp.async (2-stage); tf32 conversion at fragment-load time.
// a*b ~= ah*bh + ah*bl  (error ~ al*b ~ 2^-11 rel; budget-checked vs 1e-3)
// MODE 0: per-head projection  Y[h] = X @ W[h]^T + b[h]   (z = head, SEL picks out buffer)
// MODE 1: scores S = qh @ kh^T                            (z = b*H+h)
// MODE 2: O = P @ vh (NN), scatter rows into cat layout   (z = b*H+h)
// MODE 3: out = cat' @ Wo'^T + bo                         (z = 0)

#define BM 128
#define BNT 64
#define BK 16
#define AROW 20          // BK + 4 pad (floats)
#define BROW_NT 20       // BK + 4 pad
#define BROW_NN 68       // BNT + 4 pad

template<int MODE, int SEL>
__global__ __launch_bounds__(256, 2)
void gemm3t(const float* __restrict__ P0, const float* __restrict__ P1,
            const float* __restrict__ PB, float* __restrict__ PO)
{
    constexpr long BNrows = (long)CB * CN;                 // 32768
    constexpr int KD  = (MODE == 2) ? 1024 : (MODE == 3 ? 4096 : 512);
    constexpr int LDA = (MODE == 2) ? 1024 : (MODE == 3 ? 4096 : 512);
    constexpr int LDB = (MODE == 3) ? 4096 : 512;
    constexpr int LDC = (MODE == 1) ? 1024 : (MODE == 2 ? 4096 : 512);
    constexpr bool NT   = (MODE != 2);
    constexpr bool HASB = (MODE == 0 || MODE == 3);
    constexpr int ABUF = BM * AROW;                         // floats per A stage
    constexpr int BBUF = NT ? (BNT * BROW_NT) : (BK * BROW_NN);

    const int z = blockIdx.z;
    const float* A;
    const float* Bm;
    const float* bias = nullptr;
    float* C;

    if constexpr (MODE == 0) {
        A   = P0;
        Bm  = P1 + (size_t)z * 512 * 512;
        bias = PB + (size_t)z * 512;
        float* ob = (SEL == 0) ? g_kh : (SEL == 1) ? g_vh : g_qh;
        C = ob + (size_t)z * BNrows * 512;
    } else if constexpr (MODE == 1) {
        const int b = z >> 3, h = z & 7;
        const size_t off = ((size_t)h * BNrows + (size_t)b * CN) * 512;
        A  = g_qh + off;
        Bm = g_kh + off;
        C  = g_sc + (size_t)z * CN * CN;
    } else if constexpr (MODE == 2) {
        const int b = z >> 3, h = z & 7;
        A  = g_sc + (size_t)z * CN * CN;
        Bm = g_vh + ((size_t)h * BNrows + (size_t)b * CN) * 512;
        C  = g_cat + ((size_t)b * CN * CH + h) * 512;
    } else {
        A = g_cat; Bm = g_wo; bias = PB; C = PO;
    }

    const int m0 = blockIdx.y * BM;
    const int n0 = blockIdx.x * BNT;
    const int tid = threadIdx.x;

    __shared__ __align__(16) float As[2 * ABUF];
    __shared__ __align__(16) float Bs[2 * BBUF];

    const uint32_t as_base = (uint32_t)__cvta_generic_to_shared(&As[0]);
    const uint32_t bs_base = (uint32_t)__cvta_generic_to_shared(&Bs[0]);

    // ---- cp.async source/dest mappings ----
    // A: 128 rows x 16 k = 512 float4; thread does chunks tid and tid+256.
    const int a_r  = tid >> 2;            // 0..63
    const int a_kq = (tid & 3) * 4;       // 0,4,8,12
    const float* aSrc0 = A + (size_t)(m0 + a_r) * LDA + a_kq;
    const float* aSrc1 = A + (size_t)(m0 + a_r + 64) * LDA + a_kq;
    const uint32_t aDst0 = as_base + (uint32_t)(a_r * AROW + a_kq) * 4u;
    const uint32_t aDst1 = aDst0 + (uint32_t)(64 * AROW) * 4u;

    // B: 256 float4, one per thread.
    const float* bSrc;
    uint32_t bDst;
    if constexpr (NT) {               // B[n0+r][t*BK + kq..+3] -> Bs[r][kq..]
        const int b_r  = tid >> 2;    // 0..63
        const int b_kq = (tid & 3) * 4;
        bSrc = Bm + (size_t)(n0 + b_r) * LDB + b_kq;
        bDst = bs_base + (uint32_t)(b_r * BROW_NT + b_kq) * 4u;
    } else {                          // B[t*BK+kr][n0+nq..+3] -> Bs[kr][nq..]
        const int b_kr = tid >> 4;    // 0..15
        const int b_nq = (tid & 15) * 4;
        bSrc = Bm + (size_t)b_kr * LDB + n0 + b_nq;
        bDst = bs_base + (uint32_t)(b_kr * BROW_NN + b_nq) * 4u;
    }

    const int warp = tid >> 5, lane = tid & 31;
    const int wm = (warp & 3) * 32;
    const int wn = (warp >> 2) * 32;
    const int grp = lane >> 2, qd = lane & 3;

    float acc[2][4][4];
    #pragma unroll
    for (int i = 0; i < 2; i++)
        #pragma unroll
        for (int j = 0; j < 4; j++)
            #pragma unroll
            for (int t = 0; t < 4; t++) acc[i][j][t] = 0.f;

    // ---- prologue: issue tile 0 into buffer 0 ----
    {
        cpa16(aDst0, aSrc0);
        cpa16(aDst1, aSrc1);
        cpa16(bDst, bSrc);
        cpa_commit();
    }

    const int ktiles = KD / BK;
    for (int t = 0; t < ktiles; ++t) {
        const int cur = t & 1;
        cpa_wait0();
        __syncthreads();

        if (t + 1 < ktiles) {
            const int nxt = cur ^ 1;
            const size_t koff = (size_t)(t + 1) * BK;
            cpa16(aDst0 + (uint32_t)(nxt * ABUF) * 4u, aSrc0 + koff);
            cpa16(aDst1 + (uint32_t)(nxt * ABUF) * 4u, aSrc1 + koff);
            if constexpr (NT) cpa16(bDst + (uint32_t)(nxt * BBUF) * 4u, bSrc + koff);
            else              cpa16(bDst + (uint32_t)(nxt * BBUF) * 4u, bSrc + koff * LDB);
            cpa_commit();
        }

        const float* as = &As[cur * ABUF];
        const float* bs = &Bs[cur * BBUF];

        #pragma unroll
        for (int ks = 0; ks < 2; ++ks) {
            const int k0 = ks * 8 + qd;
            const int k1 = k0 + 4;

            // A fragments: single-tf32 (no split)
            unsigned ah[2][4];
            #pragma unroll
            for (int fm = 0; fm < 2; fm++) {
                const int r0 = wm + fm * 16 + grp;
                ah[fm][0] = tf32_hi(as[r0 * AROW + k0]);
                ah[fm][1] = tf32_hi(as[(r0 + 8) * AROW + k0]);
                ah[fm][2] = tf32_hi(as[r0 * AROW + k1]);
                ah[fm][3] = tf32_hi(as[(r0 + 8) * AROW + k1]);
            }
            // B fragments: hi/lo split
            unsigned bh[4][2], bl[4][2];
            #pragma unroll
            for (int fn = 0; fn < 4; fn++) {
                const int c = wn + fn * 8 + grp;
                float w0, w1;
                if constexpr (NT) { w0 = bs[c * BROW_NT + k0]; w1 = bs[c * BROW_NT + k1]; }
                else              { w0 = bs[k0 * BROW_NN + c]; w1 = bs[k1 * BROW_NN + c]; }
                tf32_split_u(w0, bh[fn][0], bl[fn][0]);
                tf32_split_u(w1, bh[fn][1], bl[fn][1]);
            }

            #pragma unroll
            for (int fm = 0; fm < 2; fm++) {
                #pragma unroll
                for (int fn = 0; fn < 4; fn++) {
                    mma_tf32(acc[fm][fn], ah[fm][0], ah[fm][1], ah[fm][2], ah[fm][3],
                             bh[fn][0], bh[fn][1]);                       // a*bh
                    mma_tf32(acc[fm][fn], ah[fm][0], ah[fm][1], ah[fm][2], ah[fm][3],
                             bl[fn][0], bl[fn][1]);                       // a*bl
                }
            }
        }
        // no trailing sync: next-iter wait+syncthreads orders reuse of this buffer
    }

    // ---- epilogue ----
    #pragma unroll
    for (int fm = 0; fm < 2; fm++) {
        const int r = m0 + wm + fm * 16 + grp;
        #pragma unroll
        for (int fn = 0; fn < 4; fn++) {
            const int cc = n0 + wn + fn * 8 + qd * 2;
            float2 v0 = make_float2(acc[fm][fn][0], acc[fm][fn][1]);
            float2 v1 = make_float2(acc[fm][fn][2], acc[fm][fn][3]);
            if constexpr (HASB) {
                const float2 bb = *(const float2*)(bias + cc);
                v0.x += bb.x; v0.y += bb.y; v1.x += bb.x; v1.y += bb.y;
            }
            *(float2*)(C + (size_t)r * LDC + cc)       = v0;
            *(float2*)(C + (size_t)(r + 8) * LDC + cc) = v1;
        }
    }
}

// ---------------- softmax over score rows (scale folded in) ----------------
__global__ void softmax_k()
{
    const size_t row = blockIdx.x;                    // B*H*N = 262144 rows
    float* p = g_sc + row * 1024;
    const int tid = threadIdx.x;                      // 256 threads, 4 elems each
    float4 v = reinterpret_cast<float4*>(p)[tid];

    float m = fmaxf(fmaxf(v.x, v.y), fmaxf(v.z, v.w));
    #pragma unroll
    for (int o = 16; o; o >>= 1) m = fmaxf(m, __shfl_xor_sync(0xffffffffu, m, o));
    __shared__ float sm[8];
    if ((tid & 31) == 0) sm[tid >> 5] = m;
    __syncthreads();
    const float mm = fmaxf(fmaxf(fmaxf(sm[0], sm[1]), fmaxf(sm[2], sm[3])),
                           fmaxf(fmaxf(sm[4], sm[5]), fmaxf(sm[6], sm[7])));

    const float INV_TAU = 0.044194173824159216f;      // 1/sqrt(512)
    v.x = __expf((v.x - mm) * INV_TAU);
    v.y = __expf((v.y - mm) * INV_TAU);
    v.z = __expf((v.z - mm) * INV_TAU);
    v.w = __expf((v.w - mm) * INV_TAU);

    float s = v.x + v.y + v.z + v.w;
    #pragma unroll
    for (int o = 16; o; o >>= 1) s += __shfl_xor_sync(0xffffffffu, s, o);
    __shared__ float ss[8];
    if ((tid & 31) == 0) ss[tid >> 5] = s;
    __syncthreads();
    const float tot = ss[0] + ss[1] + ss[2] + ss[3] + ss[4] + ss[5] + ss[6] + ss[7];

    const float inv = 1.0f / tot;
    v.x *= inv; v.y *= inv; v.z *= inv; v.w *= inv;
    reinterpret_cast<float4*>(p)[tid] = v;
}

// ---------------- Wo column permutation: col d*H+h -> h*D+d ----------------
__global__ void permute_wo(const float* __restrict__ Wo)
{
    const int i = blockIdx.x * blockDim.x + threadIdx.x;  // 512*4096 = 2097152
    if (i >= 512 * 4096) return;
    const int e2 = i >> 12;
    const int c  = i & 4095;
    const int h  = c >> 9;
    const int d  = c & 511;
    g_wo[i] = Wo[(e2 << 12) + d * 8 + h];
}

// ---------------- launch ----------------
extern "C" void kernel_launch(void* const* d_in, const int* in_sizes, int n_in,
                              void* d_out, int out_size)
{
    (void)in_sizes; (void)n_in; (void)out_size;
    const float* k  = (const float*)d_in[0];
    const float* v  = (const float*)d_in[1];
    const float* q  = (const float*)d_in[2];
    const float* Wk = (const float*)d_in[3];
    const float* bk = (const float*)d_in[4];
    const float* Wv = (const float*)d_in[5];
    const float* bv = (const float*)d_in[6];
    const float* Wq = (const float*)d_in[7];
    const float* bq = (const float*)d_in[8];
    const float* Wo = (const float*)d_in[9];
    const float* bo = (const float*)d_in[10];
    float* out = (float*)d_out;

    const dim3 blk(256);

    permute_wo<<<8192, 256>>>(Wo);

    // per-head projections: grid (N'/64=8, M/128=256, H=8)
    gemm3t<0, 0><<<dim3(8, 256, 8), blk>>>(k, Wk, bk, nullptr);
    gemm3t<0, 1><<<dim3(8, 256, 8), blk>>>(v, Wv, bv, nullptr);
    gemm3t<0, 2><<<dim3(8, 256, 8), blk>>>(q, Wq, bq, nullptr);

    // scores: grid (1024/64=16, 1024/128=8, B*H=256)
    gemm3t<1, 0><<<dim3(16, 8, 256), blk>>>(nullptr, nullptr, nullptr, nullptr);

    // softmax over 262144 rows
    softmax_k<<<262144, 256>>>();

    // PV: grid (512/64=8, 1024/128=8, 256)
    gemm3t<2, 0><<<dim3(8, 8, 256), blk>>>(nullptr, nullptr, nullptr, nullptr);

    // output projection: grid (512/64=8, 32768/128=256, 1)
    gemm3t<3, 0><<<dim3(8, 256, 1), blk>>>(nullptr, nullptr, bo, out);
}